// round 14
// baseline (speedup 1.0000x reference)
#include <cuda_runtime.h>
#include <cuda_fp16.h>
#include <cstdint>

#define NN 100000
#define NE 3200000
#define C1 256
#define C2 64
#define C3 128
#define NBLK ((NN + 255) / 256)   // 391
#define FILL_BLKS (NE / 2 / 256)  // 6250
#define G1_BLKS ((NN + 127) / 128) // 782

// Scratch (static device globals — no allocation allowed)
__device__ __half2 g_hs1h[(size_t)NN * C2 / 2];  // dinv * (x @ W1), fp16
__device__ __half2 g_rs1h[(size_t)NN * C2 / 2];  // dinv * relu(dinv*agg1 + b1), fp16
__device__ __half2 g_a2h [(size_t)NN * C2 / 2];  // dinv * layer2 aggregate, fp16
__device__ int     g_deg[NN];                    // in-degree WITHOUT self loop
__device__ float   g_dinv[NN];
__device__ float   g_gsum[C3];
__device__ int     g_ctr;                        // CSR base ticket
__device__ int     g_done;                       // gemm2mean completion counter
// CSR of in-edges (per-node ranges disjoint, NOT monotonic)
__device__ int   g_off[NN];
__device__ int   g_cur[NN];
__device__ int   g_csrc[NE];

// ---------------- MMA helpers ----------------
__device__ __forceinline__ uint32_t s2u(const void* p) {
    uint32_t a;
    asm("{ .reg .u64 t; cvta.to.shared.u64 t, %1; cvt.u32.u64 %0, t; }" : "=r"(a) : "l"(p));
    return a;
}
#define LDSM4(r0, r1, r2, r3, addr) \
    asm volatile("ldmatrix.sync.aligned.m8n8.x4.shared.b16 {%0,%1,%2,%3}, [%4];" \
                 : "=r"(r0), "=r"(r1), "=r"(r2), "=r"(r3) : "r"(addr))
#define LDSM2T(r0, r1, addr) \
    asm volatile("ldmatrix.sync.aligned.m8n8.x2.trans.shared.b16 {%0,%1}, [%2];" \
                 : "=r"(r0), "=r"(r1) : "r"(addr))
#define MMA16816(d, a, b) \
    asm volatile("mma.sync.aligned.m16n8k16.row.col.f32.f16.f16.f32 " \
                 "{%0,%1,%2,%3}, {%4,%5,%6,%7}, {%8,%9}, {%0,%1,%2,%3};" \
                 : "+f"((d)[0]), "+f"((d)[1]), "+f"((d)[2]), "+f"((d)[3]) \
                 : "r"((a)[0]), "r"((a)[1]), "r"((a)[2]), "r"((a)[3]), \
                   "r"((b)[0]), "r"((b)[1]))
#define SWZ(off) ((off) ^ (((off) >> 3) & 0x70))

// fp16 packed accumulate of uint4 (8 halves) into 4 half2 accumulators
__device__ __forceinline__ void hacc4(__half2* h, uint4 v) {
    h[0] = __hadd2(h[0], *(__half2*)&v.x);
    h[1] = __hadd2(h[1], *(__half2*)&v.y);
    h[2] = __hadd2(h[2], *(__half2*)&v.z);
    h[3] = __hadd2(h[3], *(__half2*)&v.w);
}

// packed cross-group reduction: h[t] += shfl_xor(h[t], 8); then 16
__device__ __forceinline__ void hred4(__half2* h) {
#pragma unroll
    for (int t = 0; t < 4; t++) {
        uint32_t u = *(uint32_t*)&h[t];
        uint32_t v = __shfl_xor_sync(0xffffffffu, u, 8);
        h[t] = __hadd2(h[t], *(__half2*)&v);
        u = *(uint32_t*)&h[t];
        v = __shfl_xor_sync(0xffffffffu, u, 16);
        h[t] = __hadd2(h[t], *(__half2*)&v);
    }
}

// ---------------- degree count (also zeroes small scalars) ----------------
__global__ void degcnt_k(const int* __restrict__ ei) {
    if (blockIdx.x == 0) {
        if (threadIdx.x < C3) g_gsum[threadIdx.x] = 0.f;
        if (threadIdx.x == C3) g_ctr = 0;
        if (threadIdx.x == C3 + 1) g_done = 0;
    }
    int e2 = blockIdx.x * blockDim.x + threadIdx.x;
    if (e2 >= NE / 2) return;
    int2 d = *(const int2*)(ei + NE + e2 * 2);
    atomicAdd(&g_deg[d.x], 1);
    atomicAdd(&g_deg[d.y], 1);
}

// ------- fused scan: block-local inclusive scan + atomic-ticket base -------
__global__ void scanF_k() {
    __shared__ int sm[256];
    __shared__ int base_s;
    int t = threadIdx.x;
    int i = blockIdx.x * 256 + t;
    int dg = (i < NN) ? g_deg[i] : 0;
    if (i < NN) g_dinv[i] = rsqrtf((float)(dg + 1));   // +1 self loop
    sm[t] = dg;
    __syncthreads();
    for (int o = 1; o < 256; o <<= 1) {
        int add = (t >= o) ? sm[t - o] : 0;
        __syncthreads();
        sm[t] += add;
        __syncthreads();
    }
    if (t == 255) base_s = atomicAdd(&g_ctr, sm[255]);
    __syncthreads();
    if (i < NN) {
        int off = base_s + sm[t] - dg;
        g_off[i] = off;
        g_cur[i] = off;
    }
}

// ------- fused gemm1 + fill: gemm blocks FIRST; reg-double-buffered loads -------
__global__ void fillgemm_k(const int* __restrict__ ei,
                           const float* __restrict__ x,
                           const float* __restrict__ W1) {
    __shared__ __align__(128) __half As[128 * 64];
    __shared__ __align__(128) __half Bs[64 * 64];

    if (blockIdx.x >= G1_BLKS) {
        int e2 = (blockIdx.x - G1_BLKS) * 256 + threadIdx.x;
        int2 s = *(const int2*)(ei + e2 * 2);
        int2 d = *(const int2*)(ei + NE + e2 * 2);
        int p0 = atomicAdd(&g_cur[d.x], 1);
        g_csrc[p0] = s.x;
        int p1 = atomicAdd(&g_cur[d.y], 1);
        g_csrc[p1] = s.y;
        return;
    }

    // ---- gemm1: hs1 = fp16(dinv * (x @ W1)), fp32 accum ----
    const int tid = threadIdx.x;
    const int lane = tid & 31, warp = tid >> 5;
    const int wm = warp >> 1, wn = warp & 1;
    const int row0 = blockIdx.x * 128;
    const uint32_t smA = s2u(As), smB = s2u(Bs);

    // per-thread load coordinates
    const int ar = tid >> 4, ac4 = tid & 15;          // A: rows ar, ar+16*.., col c4
    const int agrow0 = row0 + ar;

    float acc[2][4][4];
#pragma unroll
    for (int t = 0; t < 2; t++)
#pragma unroll
        for (int nt = 0; nt < 4; nt++)
#pragma unroll
            for (int q = 0; q < 4; q++) acc[t][nt][q] = 0.f;

    float4 xr[8], wr[4];
    // preload chunk 0
#pragma unroll
    for (int i = 0; i < 8; i++) {
        int grow = agrow0 + i * 16;
        xr[i] = make_float4(0.f, 0.f, 0.f, 0.f);
        if (grow < NN) xr[i] = *(const float4*)(x + (size_t)grow * C1 + ac4 * 4);
    }
#pragma unroll
    for (int i = 0; i < 4; i++)
        wr[i] = *(const float4*)(W1 + (size_t)(ar + i * 16) * C2 + ac4 * 4);

    for (int kc = 0; kc < C1; kc += 64) {
        __syncthreads();   // prior MMA done reading smem (no-op first iter)
        // store regs -> smem (fp16, swizzled)
#pragma unroll
        for (int i = 0; i < 8; i++) {
            uint32_t off = (uint32_t)((ar + i * 16) * 128 + ac4 * 8);
            *(half2*)((char*)As + SWZ(off))     = __floats2half2_rn(xr[i].x, xr[i].y);
            *(half2*)((char*)As + SWZ(off + 4)) = __floats2half2_rn(xr[i].z, xr[i].w);
        }
#pragma unroll
        for (int i = 0; i < 4; i++) {
            uint32_t off = (uint32_t)((ar + i * 16) * 128 + ac4 * 8);
            *(half2*)((char*)Bs + SWZ(off))     = __floats2half2_rn(wr[i].x, wr[i].y);
            *(half2*)((char*)Bs + SWZ(off + 4)) = __floats2half2_rn(wr[i].z, wr[i].w);
        }
        __syncthreads();   // smem ready

        // prefetch next chunk while MMA runs
        if (kc + 64 < C1) {
            int kn = kc + 64;
#pragma unroll
            for (int i = 0; i < 8; i++) {
                int grow = agrow0 + i * 16;
                xr[i] = make_float4(0.f, 0.f, 0.f, 0.f);
                if (grow < NN) xr[i] = *(const float4*)(x + (size_t)grow * C1 + kn + ac4 * 4);
            }
#pragma unroll
            for (int i = 0; i < 4; i++)
                wr[i] = *(const float4*)(W1 + (size_t)(kn + ar + i * 16) * C2 + ac4 * 4);
        }

#pragma unroll
        for (int kk = 0; kk < 64; kk += 16) {
            uint32_t a[2][4], b[4][2];
#pragma unroll
            for (int t = 0; t < 2; t++) {
                uint32_t off = (uint32_t)((wm * 32 + t * 16 + (lane & 15)) * 128
                                          + (kk + (lane >> 4) * 8) * 2);
                LDSM4(a[t][0], a[t][1], a[t][2], a[t][3], smA + SWZ(off));
            }
#pragma unroll
            for (int nt = 0; nt < 4; nt++) {
                uint32_t off = (uint32_t)((kk + (lane & 15)) * 128
                                          + (wn * 32 + nt * 8) * 2);
                LDSM2T(b[nt][0], b[nt][1], smB + SWZ(off));
            }
#pragma unroll
            for (int t = 0; t < 2; t++)
#pragma unroll
                for (int nt = 0; nt < 4; nt++) MMA16816(acc[t][nt], a[t], b[nt]);
        }
    }

#pragma unroll
    for (int t = 0; t < 2; t++) {
        int ra = row0 + wm * 32 + t * 16 + (lane >> 2);
        int rb = ra + 8;
        float dva = (ra < NN) ? g_dinv[ra] : 0.f;
        float dvb = (rb < NN) ? g_dinv[rb] : 0.f;
#pragma unroll
        for (int nt = 0; nt < 4; nt++) {
            int col2 = wn * 16 + nt * 4 + (lane & 3);
            if (ra < NN)
                g_hs1h[(size_t)ra * 32 + col2] =
                    __floats2half2_rn(acc[t][nt][0] * dva, acc[t][nt][1] * dva);
            if (rb < NN)
                g_hs1h[(size_t)rb * 32 + col2] =
                    __floats2half2_rn(acc[t][nt][2] * dvb, acc[t][nt][3] * dvb);
        }
    }
}

// ---- pull layer1: warp/node, 4 edges in flight, fp16 HADD2, offset-shfl ----
__global__ void pull1_k(const float* __restrict__ b1) {
    int w = (blockIdx.x * blockDim.x + threadIdx.x) >> 5;
    if (w >= NN) return;
    int lane = threadIdx.x & 31;
    int q = lane >> 3, ql = lane & 7;
    const char* base = (const char*)g_hs1h + ql * 16;
    int beg = g_off[w];
    int end = beg + g_deg[w];
    __half2 h[4];
    if (q == 0) {
        uint4 v = *(const uint4*)(base + w * 128);   // self loop
        h[0] = *(__half2*)&v.x; h[1] = *(__half2*)&v.y;
        h[2] = *(__half2*)&v.z; h[3] = *(__half2*)&v.w;
    } else {
        __half2 z = __floats2half2_rn(0.f, 0.f);
        h[0] = z; h[1] = z; h[2] = z; h[3] = z;
    }
    int i = beg;
    while (i + 32 <= end) {
        int off = __ldg(g_csrc + i + lane) * 128;    // byte offset, <2^31
#pragma unroll
        for (int j = 0; j < 32; j += 4) {
            int so = __shfl_sync(0xffffffffu, off, j + q);
            hacc4(h, *(const uint4*)(base + so));
        }
        i += 32;
    }
    if (i < end) {
        int n = end - i;
        int off = 0;
        if (lane < n) off = __ldg(g_csrc + i + lane) * 128;
        for (int j = 0; j < n; j += 4) {
            int e = j + q;
            int so = __shfl_sync(0xffffffffu, off, e & 31);
            if (e < n)
                hacc4(h, *(const uint4*)(base + so));
        }
    }
    hred4(h);
    if (q == 0) {
        float dv = g_dinv[w];
        float4 b0 = ((const float4*)b1)[ql * 2];
        float4 b1v = ((const float4*)b1)[ql * 2 + 1];
        float2 f0 = __half22float2(h[0]), f1 = __half22float2(h[1]);
        float2 f2 = __half22float2(h[2]), f3 = __half22float2(h[3]);
        float r0 = fmaxf(f0.x * dv + b0.x, 0.f) * dv;
        float r1 = fmaxf(f0.y * dv + b0.y, 0.f) * dv;
        float r2 = fmaxf(f1.x * dv + b0.z, 0.f) * dv;
        float r3 = fmaxf(f1.y * dv + b0.w, 0.f) * dv;
        float r4 = fmaxf(f2.x * dv + b1v.x, 0.f) * dv;
        float r5 = fmaxf(f2.y * dv + b1v.y, 0.f) * dv;
        float r6 = fmaxf(f3.x * dv + b1v.z, 0.f) * dv;
        float r7 = fmaxf(f3.y * dv + b1v.w, 0.f) * dv;
        uint4 o;
        *(__half2*)&o.x = __floats2half2_rn(r0, r1);
        *(__half2*)&o.y = __floats2half2_rn(r2, r3);
        *(__half2*)&o.z = __floats2half2_rn(r4, r5);
        *(__half2*)&o.w = __floats2half2_rn(r6, r7);
        ((uint4*)(g_rs1h + (size_t)w * 32))[ql] = o;
    }
}

// ---- pull layer2: a2 = fp16(dinv * (rs1[d] + sum rs1[s])) ----
__global__ void pull2_k() {
    int w = (blockIdx.x * blockDim.x + threadIdx.x) >> 5;
    if (w >= NN) return;
    int lane = threadIdx.x & 31;
    int q = lane >> 3, ql = lane & 7;
    const char* base = (const char*)g_rs1h + ql * 16;
    int beg = g_off[w];
    int end = beg + g_deg[w];
    __half2 h[4];
    if (q == 0) {
        uint4 v = *(const uint4*)(base + w * 128);   // self loop
        h[0] = *(__half2*)&v.x; h[1] = *(__half2*)&v.y;
        h[2] = *(__half2*)&v.z; h[3] = *(__half2*)&v.w;
    } else {
        __half2 z = __floats2half2_rn(0.f, 0.f);
        h[0] = z; h[1] = z; h[2] = z; h[3] = z;
    }
    int i = beg;
    while (i + 32 <= end) {
        int off = __ldg(g_csrc + i + lane) * 128;
#pragma unroll
        for (int j = 0; j < 32; j += 4) {
            int so = __shfl_sync(0xffffffffu, off, j + q);
            hacc4(h, *(const uint4*)(base + so));
        }
        i += 32;
    }
    if (i < end) {
        int n = end - i;
        int off = 0;
        if (lane < n) off = __ldg(g_csrc + i + lane) * 128;
        for (int j = 0; j < n; j += 4) {
            int e = j + q;
            int so = __shfl_sync(0xffffffffu, off, e & 31);
            if (e < n)
                hacc4(h, *(const uint4*)(base + so));
        }
    }
    hred4(h);
    if (q == 0) {
        float dv = g_dinv[w];
        float2 f0 = __half22float2(h[0]), f1 = __half22float2(h[1]);
        float2 f2 = __half22float2(h[2]), f3 = __half22float2(h[3]);
        uint4 o;
        *(__half2*)&o.x = __floats2half2_rn(f0.x * dv, f0.y * dv);
        *(__half2*)&o.y = __floats2half2_rn(f1.x * dv, f1.y * dv);
        *(__half2*)&o.z = __floats2half2_rn(f2.x * dv, f2.y * dv);
        *(__half2*)&o.w = __floats2half2_rn(f3.x * dv, f3.y * dv);
        ((uint4*)(g_a2h + (size_t)w * 32))[ql] = o;
    }
}

// --- GEMM2 + mean + FC fused: last block computes final output ---
__global__ void gemm2mean_k(const float* __restrict__ W2, const float* __restrict__ b2,
                            const float* __restrict__ fcW, const float* __restrict__ fcb,
                            float* __restrict__ out) {
    __shared__ __align__(128) __half As[128 * 64];
    __shared__ __align__(128) __half Bs[2][64 * 64];
    __shared__ float colsum[C3];
    __shared__ int isLast;
    const int tid = threadIdx.x;
    const int lane = tid & 31, warp = tid >> 5;
    const int wm = warp >> 1, wn = warp & 1;
    const int row0 = blockIdx.x * 128;
    const uint32_t smA = s2u(As), smB = s2u(Bs);

    if (tid < C3) colsum[tid] = 0.f;

#pragma unroll
    for (int i = 0; i < 8; i++) {
        int li = tid + i * 256;
        int r = li >> 5, c4 = li & 31;
        float4 v = *(const float4*)(W2 + (size_t)r * C3 + c4 * 4);
        int ncol = c4 * 4;
        int tile = ncol >> 6;
        uint32_t off = (uint32_t)(r * 128 + (ncol & 63) * 2);
        char* base = (char*)Bs + tile * 8192;
        *(half2*)(base + SWZ(off))     = __floats2half2_rn(v.x, v.y);
        *(half2*)(base + SWZ(off + 4)) = __floats2half2_rn(v.z, v.w);
    }
#pragma unroll
    for (int i = 0; i < 4; i++) {
        int li = tid + i * 256;
        int r = li >> 3, c = li & 7;
        int grow = row0 + r;
        uint4 v = make_uint4(0u, 0u, 0u, 0u);
        if (grow < NN) v = ((const uint4*)(g_a2h + (size_t)grow * 32))[c];
        *(uint4*)((char*)As + SWZ((uint32_t)(r * 128 + c * 16))) = v;
    }
    __syncthreads();

    float acc[2][8][4];
#pragma unroll
    for (int t = 0; t < 2; t++)
#pragma unroll
        for (int nt = 0; nt < 8; nt++)
#pragma unroll
            for (int q = 0; q < 4; q++) acc[t][nt][q] = 0.f;

#pragma unroll
    for (int kk = 0; kk < 64; kk += 16) {
        uint32_t a[2][4], b[8][2];
#pragma unroll
        for (int t = 0; t < 2; t++) {
            uint32_t off = (uint32_t)((wm * 32 + t * 16 + (lane & 15)) * 128
                                      + (kk + (lane >> 4) * 8) * 2);
            LDSM4(a[t][0], a[t][1], a[t][2], a[t][3], smA + SWZ(off));
        }
#pragma unroll
        for (int nt = 0; nt < 8; nt++) {
            uint32_t off = (uint32_t)((kk + (lane & 15)) * 128 + (nt * 8) * 2);
            LDSM2T(b[nt][0], b[nt][1], smB + wn * 8192 + SWZ(off));
        }
#pragma unroll
        for (int t = 0; t < 2; t++)
#pragma unroll
            for (int nt = 0; nt < 8; nt++) MMA16816(acc[t][nt], a[t], b[nt]);
    }

#pragma unroll
    for (int nt = 0; nt < 8; nt++) {
        int c0 = wn * 64 + nt * 8 + (lane & 3) * 2;
        float bias0 = b2[c0], bias1 = b2[c0 + 1];
        float s0 = 0.f, s1 = 0.f;
#pragma unroll
        for (int t = 0; t < 2; t++) {
            int ra = row0 + wm * 32 + t * 16 + (lane >> 2);
            int rb = ra + 8;
            if (ra < NN) { s0 += fmaxf(acc[t][nt][0] + bias0, 0.f);
                           s1 += fmaxf(acc[t][nt][1] + bias1, 0.f); }
            if (rb < NN) { s0 += fmaxf(acc[t][nt][2] + bias0, 0.f);
                           s1 += fmaxf(acc[t][nt][3] + bias1, 0.f); }
        }
        s0 += __shfl_xor_sync(0xffffffffu, s0, 4);
        s0 += __shfl_xor_sync(0xffffffffu, s0, 8);
        s0 += __shfl_xor_sync(0xffffffffu, s0, 16);
        s1 += __shfl_xor_sync(0xffffffffu, s1, 4);
        s1 += __shfl_xor_sync(0xffffffffu, s1, 8);
        s1 += __shfl_xor_sync(0xffffffffu, s1, 16);
        if (lane < 4) {
            atomicAdd(&colsum[c0], s0);
            atomicAdd(&colsum[c0 + 1], s1);
        }
    }
    __syncthreads();
    if (tid < C3) atomicAdd(&g_gsum[tid], colsum[tid]);
    __threadfence();
    __syncthreads();
    if (tid == 0) isLast = (atomicAdd(&g_done, 1) == (int)gridDim.x - 1) ? 1 : 0;
    __syncthreads();
    if (isLast && tid < 64) {
        int k = tid >> 5, l = tid & 31;
        float s = 0.f;
        for (int f = l; f < C3; f += 32)
            s += atomicAdd(&g_gsum[f], 0.f) * fcW[k * C3 + f];
#pragma unroll
        for (int o = 16; o; o >>= 1) s += __shfl_down_sync(0xffffffffu, s, o);
        if (l == 0) out[k] = s * (1.f / NN) + fcb[k];
    }
}

extern "C" void kernel_launch(void* const* d_in, const int* in_sizes, int n_in,
                              void* d_out, int out_size) {
    const float* x   = (const float*)d_in[0];
    const int*   ei  = (const int*)d_in[1];          // int32 (jax x64 disabled)
    const float* W1  = (const float*)d_in[2];
    const float* b1  = (const float*)d_in[3];
    const float* W2  = (const float*)d_in[4];
    const float* b2  = (const float*)d_in[5];
    const float* fcW = (const float*)d_in[6];
    const float* fcb = (const float*)d_in[7];
    float* out = (float*)d_out;

    void* degp = nullptr;
    cudaGetSymbolAddress(&degp, g_deg);
    cudaMemsetAsync(degp, 0, NN * sizeof(int));

    degcnt_k<<<(NE / 2 + 255) / 256, 256>>>(ei);
    scanF_k<<<NBLK, 256>>>();
    fillgemm_k<<<G1_BLKS + FILL_BLKS, 256>>>(ei, x, W1);   // gemm1 ∥ fill
    pull1_k<<<(NN * 32 + 255) / 256, 256>>>(b1);
    pull2_k<<<(NN * 32 + 255) / 256, 256>>>();
    gemm2mean_k<<<(NN + 127) / 128, 256>>>(W2, b2, fcW, fcb, out);  // + fused FC
}

// round 16
// speedup vs baseline: 1.1152x; 1.1152x over previous
#include <cuda_runtime.h>
#include <cuda_fp16.h>
#include <cstdint>

#define NN 100000
#define NE 3200000
#define C1 256
#define C2 64
#define C3 128
#define NBLK ((NN + 255) / 256)   // 391

// Scratch (static device globals — no allocation allowed)
__device__ __half2 g_hs1h[(size_t)NN * C2 / 2];  // dinv * (x @ W1), fp16
__device__ __half2 g_rs1h[(size_t)NN * C2 / 2];  // dinv * relu(dinv*agg1 + b1), fp16
__device__ __half2 g_a2h [(size_t)NN * C2 / 2];  // dinv * layer2 aggregate, fp16
__device__ int     g_deg[NN];                    // in-degree WITHOUT self loop
__device__ float   g_dinv[NN];
__device__ float   g_gsum[C3];
__device__ int     g_ctr;                        // CSR base ticket
__device__ int     g_done;                       // gemm2mean completion counter
// CSR of in-edges (per-node ranges disjoint, NOT monotonic)
__device__ int   g_off[NN];
__device__ int   g_cur[NN];
__device__ int   g_csrc[NE];

// ---------------- MMA helpers ----------------
__device__ __forceinline__ uint32_t s2u(const void* p) {
    uint32_t a;
    asm("{ .reg .u64 t; cvta.to.shared.u64 t, %1; cvt.u32.u64 %0, t; }" : "=r"(a) : "l"(p));
    return a;
}
#define LDSM4(r0, r1, r2, r3, addr) \
    asm volatile("ldmatrix.sync.aligned.m8n8.x4.shared.b16 {%0,%1,%2,%3}, [%4];" \
                 : "=r"(r0), "=r"(r1), "=r"(r2), "=r"(r3) : "r"(addr))
#define LDSM2T(r0, r1, addr) \
    asm volatile("ldmatrix.sync.aligned.m8n8.x2.trans.shared.b16 {%0,%1}, [%2];" \
                 : "=r"(r0), "=r"(r1) : "r"(addr))
#define MMA16816(d, a, b) \
    asm volatile("mma.sync.aligned.m16n8k16.row.col.f32.f16.f16.f32 " \
                 "{%0,%1,%2,%3}, {%4,%5,%6,%7}, {%8,%9}, {%0,%1,%2,%3};" \
                 : "+f"((d)[0]), "+f"((d)[1]), "+f"((d)[2]), "+f"((d)[3]) \
                 : "r"((a)[0]), "r"((a)[1]), "r"((a)[2]), "r"((a)[3]), \
                   "r"((b)[0]), "r"((b)[1]))
#define SWZ(off) ((off) ^ (((off) >> 3) & 0x70))

// fp16 packed accumulate of uint4 (8 halves) into 4 half2 accumulators
__device__ __forceinline__ void hacc4(__half2* h, uint4 v) {
    h[0] = __hadd2(h[0], *(__half2*)&v.x);
    h[1] = __hadd2(h[1], *(__half2*)&v.y);
    h[2] = __hadd2(h[2], *(__half2*)&v.z);
    h[3] = __hadd2(h[3], *(__half2*)&v.w);
}

// packed cross-group reduction: h[t] += shfl_xor 8, then 16
__device__ __forceinline__ void hred4(__half2* h) {
#pragma unroll
    for (int t = 0; t < 4; t++) {
        uint32_t u = *(uint32_t*)&h[t];
        uint32_t v = __shfl_xor_sync(0xffffffffu, u, 8);
        h[t] = __hadd2(h[t], *(__half2*)&v);
        u = *(uint32_t*)&h[t];
        v = __shfl_xor_sync(0xffffffffu, u, 16);
        h[t] = __hadd2(h[t], *(__half2*)&v);
    }
}

// ---------------- degree count (also zeroes small scalars) ----------------
__global__ void degcnt_k(const int* __restrict__ ei) {
    if (blockIdx.x == 0) {
        if (threadIdx.x < C3) g_gsum[threadIdx.x] = 0.f;
        if (threadIdx.x == C3) g_ctr = 0;
        if (threadIdx.x == C3 + 1) g_done = 0;
    }
    int e2 = blockIdx.x * blockDim.x + threadIdx.x;
    if (e2 >= NE / 2) return;
    int2 d = *(const int2*)(ei + NE + e2 * 2);
    atomicAdd(&g_deg[d.x], 1);
    atomicAdd(&g_deg[d.y], 1);
}

// ------- fused scan: block-local inclusive scan + atomic-ticket base -------
__global__ void scanF_k() {
    __shared__ int sm[256];
    __shared__ int base_s;
    int t = threadIdx.x;
    int i = blockIdx.x * 256 + t;
    int dg = (i < NN) ? g_deg[i] : 0;
    if (i < NN) g_dinv[i] = rsqrtf((float)(dg + 1));   // +1 self loop
    sm[t] = dg;
    __syncthreads();
    for (int o = 1; o < 256; o <<= 1) {
        int add = (t >= o) ? sm[t - o] : 0;
        __syncthreads();
        sm[t] += add;
        __syncthreads();
    }
    if (t == 255) base_s = atomicAdd(&g_ctr, sm[255]);
    __syncthreads();
    if (i < NN) {
        int off = base_s + sm[t] - dg;
        g_off[i] = off;
        g_cur[i] = off;
    }
}

// ---------------- CSR fill (separate kernel — R11 structure) ----------------
__global__ void fill_k(const int* __restrict__ ei) {
    int e2 = blockIdx.x * blockDim.x + threadIdx.x;
    if (e2 >= NE / 2) return;
    int2 s = *(const int2*)(ei + e2 * 2);
    int2 d = *(const int2*)(ei + NE + e2 * 2);
    int p0 = atomicAdd(&g_cur[d.x], 1);
    g_csrc[p0] = s.x;
    int p1 = atomicAdd(&g_cur[d.y], 1);
    g_csrc[p1] = s.y;
}

// -------- GEMM1 via HMMA: hs1 = fp16(dinv * (x @ W1)), fp32 accum --------
__global__ void gemm1_k(const float* __restrict__ x, const float* __restrict__ W1) {
    __shared__ __align__(128) __half As[128 * 64];
    __shared__ __align__(128) __half Bs[64 * 64];
    const int tid = threadIdx.x;
    const int lane = tid & 31, warp = tid >> 5;
    const int wm = warp >> 1, wn = warp & 1;
    const int row0 = blockIdx.x * 128;
    const uint32_t smA = s2u(As), smB = s2u(Bs);

    float acc[2][4][4];
#pragma unroll
    for (int t = 0; t < 2; t++)
#pragma unroll
        for (int nt = 0; nt < 4; nt++)
#pragma unroll
            for (int q = 0; q < 4; q++) acc[t][nt][q] = 0.f;

    for (int kc = 0; kc < C1; kc += 64) {
#pragma unroll
        for (int i = 0; i < 8; i++) {
            int li = tid + i * 256;
            int r = li >> 4, c4 = li & 15;
            int grow = row0 + r;
            float4 v = make_float4(0.f, 0.f, 0.f, 0.f);
            if (grow < NN) v = *(const float4*)(x + (size_t)grow * C1 + kc + c4 * 4);
            uint32_t off = (uint32_t)(r * 128 + c4 * 8);
            *(half2*)((char*)As + SWZ(off))     = __floats2half2_rn(v.x, v.y);
            *(half2*)((char*)As + SWZ(off + 4)) = __floats2half2_rn(v.z, v.w);
        }
#pragma unroll
        for (int i = 0; i < 4; i++) {
            int li = tid + i * 256;
            int r = li >> 4, c4 = li & 15;
            float4 v = *(const float4*)(W1 + (size_t)(kc + r) * C2 + c4 * 4);
            uint32_t off = (uint32_t)(r * 128 + c4 * 8);
            *(half2*)((char*)Bs + SWZ(off))     = __floats2half2_rn(v.x, v.y);
            *(half2*)((char*)Bs + SWZ(off + 4)) = __floats2half2_rn(v.z, v.w);
        }
        __syncthreads();

#pragma unroll
        for (int kk = 0; kk < 64; kk += 16) {
            uint32_t a[2][4], b[4][2];
#pragma unroll
            for (int t = 0; t < 2; t++) {
                uint32_t off = (uint32_t)((wm * 32 + t * 16 + (lane & 15)) * 128
                                          + (kk + (lane >> 4) * 8) * 2);
                LDSM4(a[t][0], a[t][1], a[t][2], a[t][3], smA + SWZ(off));
            }
#pragma unroll
            for (int nt = 0; nt < 4; nt++) {
                uint32_t off = (uint32_t)((kk + (lane & 15)) * 128
                                          + (wn * 32 + nt * 8) * 2);
                LDSM2T(b[nt][0], b[nt][1], smB + SWZ(off));
            }
#pragma unroll
            for (int t = 0; t < 2; t++)
#pragma unroll
                for (int nt = 0; nt < 4; nt++) MMA16816(acc[t][nt], a[t], b[nt]);
        }
        __syncthreads();
    }

#pragma unroll
    for (int t = 0; t < 2; t++) {
        int ra = row0 + wm * 32 + t * 16 + (lane >> 2);
        int rb = ra + 8;
        float dva = (ra < NN) ? g_dinv[ra] : 0.f;
        float dvb = (rb < NN) ? g_dinv[rb] : 0.f;
#pragma unroll
        for (int nt = 0; nt < 4; nt++) {
            int col2 = wn * 16 + nt * 4 + (lane & 3);
            if (ra < NN)
                g_hs1h[(size_t)ra * 32 + col2] =
                    __floats2half2_rn(acc[t][nt][0] * dva, acc[t][nt][1] * dva);
            if (rb < NN)
                g_hs1h[(size_t)rb * 32 + col2] =
                    __floats2half2_rn(acc[t][nt][2] * dvb, acc[t][nt][3] * dvb);
        }
    }
}

// ---- pull layer1: warp/node, 4 edges in flight, fp16 HADD2, offset-shfl ----
__global__ void pull1_k(const float* __restrict__ b1) {
    int w = (blockIdx.x * blockDim.x + threadIdx.x) >> 5;
    if (w >= NN) return;
    int lane = threadIdx.x & 31;
    int q = lane >> 3, ql = lane & 7;
    const char* base = (const char*)g_hs1h + ql * 16;
    int beg = g_off[w];
    int end = beg + g_deg[w];
    __half2 h[4];
    if (q == 0) {
        uint4 v = *(const uint4*)(base + (size_t)w * 128);   // self loop
        h[0] = *(__half2*)&v.x; h[1] = *(__half2*)&v.y;
        h[2] = *(__half2*)&v.z; h[3] = *(__half2*)&v.w;
    } else {
        __half2 z = __floats2half2_rn(0.f, 0.f);
        h[0] = z; h[1] = z; h[2] = z; h[3] = z;
    }
    int i = beg;
    while (i + 32 <= end) {
        int off = __ldg(g_csrc + i + lane) * 128;    // byte offset, <2^31
#pragma unroll
        for (int j = 0; j < 32; j += 4) {
            int so = __shfl_sync(0xffffffffu, off, j + q);
            hacc4(h, *(const uint4*)(base + so));
        }
        i += 32;
    }
    if (i < end) {
        int n = end - i;
        int off = 0;
        if (lane < n) off = __ldg(g_csrc + i + lane) * 128;
        for (int j = 0; j < n; j += 4) {
            int e = j + q;
            int so = __shfl_sync(0xffffffffu, off, e & 31);
            if (e < n)
                hacc4(h, *(const uint4*)(base + so));
        }
    }
    hred4(h);
    if (q == 0) {
        float dv = g_dinv[w];
        float4 b0 = ((const float4*)b1)[ql * 2];
        float4 b1v = ((const float4*)b1)[ql * 2 + 1];
        float2 f0 = __half22float2(h[0]), f1 = __half22float2(h[1]);
        float2 f2 = __half22float2(h[2]), f3 = __half22float2(h[3]);
        float r0 = fmaxf(f0.x * dv + b0.x, 0.f) * dv;
        float r1 = fmaxf(f0.y * dv + b0.y, 0.f) * dv;
        float r2 = fmaxf(f1.x * dv + b0.z, 0.f) * dv;
        float r3 = fmaxf(f1.y * dv + b0.w, 0.f) * dv;
        float r4 = fmaxf(f2.x * dv + b1v.x, 0.f) * dv;
        float r5 = fmaxf(f2.y * dv + b1v.y, 0.f) * dv;
        float r6 = fmaxf(f3.x * dv + b1v.z, 0.f) * dv;
        float r7 = fmaxf(f3.y * dv + b1v.w, 0.f) * dv;
        uint4 o;
        *(__half2*)&o.x = __floats2half2_rn(r0, r1);
        *(__half2*)&o.y = __floats2half2_rn(r2, r3);
        *(__half2*)&o.z = __floats2half2_rn(r4, r5);
        *(__half2*)&o.w = __floats2half2_rn(r6, r7);
        ((uint4*)(g_rs1h + (size_t)w * 32))[ql] = o;
    }
}

// ---- pull layer2: a2 = fp16(dinv * (rs1[d] + sum rs1[s])) ----
__global__ void pull2_k() {
    int w = (blockIdx.x * blockDim.x + threadIdx.x) >> 5;
    if (w >= NN) return;
    int lane = threadIdx.x & 31;
    int q = lane >> 3, ql = lane & 7;
    const char* base = (const char*)g_rs1h + ql * 16;
    int beg = g_off[w];
    int end = beg + g_deg[w];
    __half2 h[4];
    if (q == 0) {
        uint4 v = *(const uint4*)(base + (size_t)w * 128);   // self loop
        h[0] = *(__half2*)&v.x; h[1] = *(__half2*)&v.y;
        h[2] = *(__half2*)&v.z; h[3] = *(__half2*)&v.w;
    } else {
        __half2 z = __floats2half2_rn(0.f, 0.f);
        h[0] = z; h[1] = z; h[2] = z; h[3] = z;
    }
    int i = beg;
    while (i + 32 <= end) {
        int off = __ldg(g_csrc + i + lane) * 128;
#pragma unroll
        for (int j = 0; j < 32; j += 4) {
            int so = __shfl_sync(0xffffffffu, off, j + q);
            hacc4(h, *(const uint4*)(base + so));
        }
        i += 32;
    }
    if (i < end) {
        int n = end - i;
        int off = 0;
        if (lane < n) off = __ldg(g_csrc + i + lane) * 128;
        for (int j = 0; j < n; j += 4) {
            int e = j + q;
            int so = __shfl_sync(0xffffffffu, off, e & 31);
            if (e < n)
                hacc4(h, *(const uint4*)(base + so));
        }
    }
    hred4(h);
    if (q == 0) {
        float dv = g_dinv[w];
        float2 f0 = __half22float2(h[0]), f1 = __half22float2(h[1]);
        float2 f2 = __half22float2(h[2]), f3 = __half22float2(h[3]);
        uint4 o;
        *(__half2*)&o.x = __floats2half2_rn(f0.x * dv, f0.y * dv);
        *(__half2*)&o.y = __floats2half2_rn(f1.x * dv, f1.y * dv);
        *(__half2*)&o.z = __floats2half2_rn(f2.x * dv, f2.y * dv);
        *(__half2*)&o.w = __floats2half2_rn(f3.x * dv, f3.y * dv);
        ((uint4*)(g_a2h + (size_t)w * 32))[ql] = o;
    }
}

// --- GEMM2 + mean + FC fused: last block computes final output ---
__global__ void gemm2mean_k(const float* __restrict__ W2, const float* __restrict__ b2,
                            const float* __restrict__ fcW, const float* __restrict__ fcb,
                            float* __restrict__ out) {
    __shared__ __align__(128) __half As[128 * 64];
    __shared__ __align__(128) __half Bs[2][64 * 64];
    __shared__ float colsum[C3];
    __shared__ int isLast;
    const int tid = threadIdx.x;
    const int lane = tid & 31, warp = tid >> 5;
    const int wm = warp >> 1, wn = warp & 1;
    const int row0 = blockIdx.x * 128;
    const uint32_t smA = s2u(As), smB = s2u(Bs);

    if (tid < C3) colsum[tid] = 0.f;

#pragma unroll
    for (int i = 0; i < 8; i++) {
        int li = tid + i * 256;
        int r = li >> 5, c4 = li & 31;
        float4 v = *(const float4*)(W2 + (size_t)r * C3 + c4 * 4);
        int ncol = c4 * 4;
        int tile = ncol >> 6;
        uint32_t off = (uint32_t)(r * 128 + (ncol & 63) * 2);
        char* base = (char*)Bs + tile * 8192;
        *(half2*)(base + SWZ(off))     = __floats2half2_rn(v.x, v.y);
        *(half2*)(base + SWZ(off + 4)) = __floats2half2_rn(v.z, v.w);
    }
#pragma unroll
    for (int i = 0; i < 4; i++) {
        int li = tid + i * 256;
        int r = li >> 3, c = li & 7;
        int grow = row0 + r;
        uint4 v = make_uint4(0u, 0u, 0u, 0u);
        if (grow < NN) v = ((const uint4*)(g_a2h + (size_t)grow * 32))[c];
        *(uint4*)((char*)As + SWZ((uint32_t)(r * 128 + c * 16))) = v;
    }
    __syncthreads();

    float acc[2][8][4];
#pragma unroll
    for (int t = 0; t < 2; t++)
#pragma unroll
        for (int nt = 0; nt < 8; nt++)
#pragma unroll
            for (int q = 0; q < 4; q++) acc[t][nt][q] = 0.f;

#pragma unroll
    for (int kk = 0; kk < 64; kk += 16) {
        uint32_t a[2][4], b[8][2];
#pragma unroll
        for (int t = 0; t < 2; t++) {
            uint32_t off = (uint32_t)((wm * 32 + t * 16 + (lane & 15)) * 128
                                      + (kk + (lane >> 4) * 8) * 2);
            LDSM4(a[t][0], a[t][1], a[t][2], a[t][3], smA + SWZ(off));
        }
#pragma unroll
        for (int nt = 0; nt < 8; nt++) {
            uint32_t off = (uint32_t)((kk + (lane & 15)) * 128 + (nt * 8) * 2);
            LDSM2T(b[nt][0], b[nt][1], smB + wn * 8192 + SWZ(off));
        }
#pragma unroll
        for (int t = 0; t < 2; t++)
#pragma unroll
            for (int nt = 0; nt < 8; nt++) MMA16816(acc[t][nt], a[t], b[nt]);
    }

#pragma unroll
    for (int nt = 0; nt < 8; nt++) {
        int c0 = wn * 64 + nt * 8 + (lane & 3) * 2;
        float bias0 = b2[c0], bias1 = b2[c0 + 1];
        float s0 = 0.f, s1 = 0.f;
#pragma unroll
        for (int t = 0; t < 2; t++) {
            int ra = row0 + wm * 32 + t * 16 + (lane >> 2);
            int rb = ra + 8;
            if (ra < NN) { s0 += fmaxf(acc[t][nt][0] + bias0, 0.f);
                           s1 += fmaxf(acc[t][nt][1] + bias1, 0.f); }
            if (rb < NN) { s0 += fmaxf(acc[t][nt][2] + bias0, 0.f);
                           s1 += fmaxf(acc[t][nt][3] + bias1, 0.f); }
        }
        s0 += __shfl_xor_sync(0xffffffffu, s0, 4);
        s0 += __shfl_xor_sync(0xffffffffu, s0, 8);
        s0 += __shfl_xor_sync(0xffffffffu, s0, 16);
        s1 += __shfl_xor_sync(0xffffffffu, s1, 4);
        s1 += __shfl_xor_sync(0xffffffffu, s1, 8);
        s1 += __shfl_xor_sync(0xffffffffu, s1, 16);
        if (lane < 4) {
            atomicAdd(&colsum[c0], s0);
            atomicAdd(&colsum[c0 + 1], s1);
        }
    }
    __syncthreads();
    if (tid < C3) atomicAdd(&g_gsum[tid], colsum[tid]);
    __threadfence();
    __syncthreads();
    if (tid == 0) isLast = (atomicAdd(&g_done, 1) == (int)gridDim.x - 1) ? 1 : 0;
    __syncthreads();
    if (isLast && tid < 64) {
        int k = tid >> 5, l = tid & 31;
        float s = 0.f;
        for (int f = l; f < C3; f += 32)
            s += atomicAdd(&g_gsum[f], 0.f) * fcW[k * C3 + f];
#pragma unroll
        for (int o = 16; o; o >>= 1) s += __shfl_down_sync(0xffffffffu, s, o);
        if (l == 0) out[k] = s * (1.f / NN) + fcb[k];
    }
}

extern "C" void kernel_launch(void* const* d_in, const int* in_sizes, int n_in,
                              void* d_out, int out_size) {
    const float* x   = (const float*)d_in[0];
    const int*   ei  = (const int*)d_in[1];          // int32 (jax x64 disabled)
    const float* W1  = (const float*)d_in[2];
    const float* b1  = (const float*)d_in[3];
    const float* W2  = (const float*)d_in[4];
    const float* b2  = (const float*)d_in[5];
    const float* fcW = (const float*)d_in[6];
    const float* fcb = (const float*)d_in[7];
    float* out = (float*)d_out;

    void* degp = nullptr;
    cudaGetSymbolAddress(&degp, g_deg);
    cudaMemsetAsync(degp, 0, NN * sizeof(int));

    degcnt_k<<<(NE / 2 + 255) / 256, 256>>>(ei);
    scanF_k<<<NBLK, 256>>>();
    gemm1_k<<<(NN + 127) / 128, 256>>>(x, W1);       // HMMA, 128-row tiles
    fill_k<<<(NE / 2 + 255) / 256, 256>>>(ei);       // CSR fill (separate)
    pull1_k<<<(NN * 32 + 255) / 256, 256>>>(b1);     // warp/node, HADD2 pulls
    pull2_k<<<(NN * 32 + 255) / 256, 256>>>();
    gemm2mean_k<<<(NN + 127) / 128, 256>>>(W2, b2, fcW, fcb, out);  // + fused FC
}